// round 8
// baseline (speedup 1.0000x reference)
#include <cuda_runtime.h>
#include <math.h>

#define B_   32
#define KV_  4096
#define H_   4096
#define NH_  32
#define NKV_ 8
#define D_   128
#define G_   4
#define QKVN ((NH_ + 2*NKV_) * D_)   // 6144
#define SCALE_ 0.08838834764831845f  // 128^-0.5
#define SPLITK 8
#define NCHUNK 16
#define CS     (KV_ / NCHUNK)        // 256 slots per chunk

// ---- scratch (device globals: no allocation) ----
__device__ float g_qkv[B_ * QKVN];                       // roped q
__device__ float g_part[SPLITK * B_ * QKVN];             // split-K GEMM partials
__device__ float g_opart[NCHUNK * B_ * NKV_ * G_ * D_];  // attn partial o
__device__ float g_ms[NCHUNK * B_ * NKV_ * G_ * 2];      // attn partial (m, sum)
__device__ float g_o[B_ * NH_ * D_];                     // attention output

// ============================================================
// Split-K GEMM (fp32 FFMA) with register-prefetch double buffering.
// ============================================================
__global__ __launch_bounds__(256) void gemm_splitk(
        const float* __restrict__ A, const float* __restrict__ W,
        float* __restrict__ P, int N, int K) {
    __shared__ float As[32][36];
    __shared__ float Ws[32][132];
    const int tid = threadIdx.x;
    const int tx = tid & 31;
    const int ty = tid >> 5;
    const int n0 = blockIdx.x * 128;
    const int kslice = K / SPLITK;
    const int kbase = blockIdx.y * kslice;

    const int m_a = tid >> 3, c_a = (tid & 7) * 4;
    const float* Aptr = &A[m_a * K + kbase + c_a];
    const float* Wptr[4];
    int n_w[4], c_w[4];
    #pragma unroll
    for (int j = 0; j < 4; j++) {
        int f = tid + j * 256;
        n_w[j] = f >> 3; c_w[j] = (f & 7) * 4;
        Wptr[j] = &W[(size_t)(n0 + n_w[j]) * K + kbase + c_w[j]];
    }

    float acc[4][4];
    #pragma unroll
    for (int i = 0; i < 4; i++)
        #pragma unroll
        for (int j = 0; j < 4; j++) acc[i][j] = 0.f;

    float4 a_reg = *(const float4*)Aptr;
    float4 w_reg[4];
    #pragma unroll
    for (int j = 0; j < 4; j++) w_reg[j] = *(const float4*)Wptr[j];

    const int nchunks = kslice / 32;
    for (int ck = 0; ck < nchunks; ck++) {
        As[c_a + 0][m_a] = a_reg.x; As[c_a + 1][m_a] = a_reg.y;
        As[c_a + 2][m_a] = a_reg.z; As[c_a + 3][m_a] = a_reg.w;
        #pragma unroll
        for (int j = 0; j < 4; j++) {
            Ws[c_w[j] + 0][n_w[j]] = w_reg[j].x;
            Ws[c_w[j] + 1][n_w[j]] = w_reg[j].y;
            Ws[c_w[j] + 2][n_w[j]] = w_reg[j].z;
            Ws[c_w[j] + 3][n_w[j]] = w_reg[j].w;
        }
        __syncthreads();

        if (ck + 1 < nchunks) {
            a_reg = *(const float4*)(Aptr + (ck + 1) * 32);
            #pragma unroll
            for (int j = 0; j < 4; j++)
                w_reg[j] = *(const float4*)(Wptr[j] + (ck + 1) * 32);
        }

        #pragma unroll
        for (int kk = 0; kk < 32; kk++) {
            float4 a4 = *(const float4*)&As[kk][ty * 4];
            float4 b4 = *(const float4*)&Ws[kk][tx * 4];
            float av[4] = {a4.x, a4.y, a4.z, a4.w};
            float bv[4] = {b4.x, b4.y, b4.z, b4.w};
            #pragma unroll
            for (int i = 0; i < 4; i++)
                #pragma unroll
                for (int j = 0; j < 4; j++) acc[i][j] += av[i] * bv[j];
        }
        __syncthreads();
    }
    float* p = P + (size_t)blockIdx.y * 32 * N;
    #pragma unroll
    for (int i = 0; i < 4; i++)
        *(float4*)&p[(ty * 4 + i) * N + n0 + tx * 4] =
            make_float4(acc[i][0], acc[i][1], acc[i][2], acc[i][3]);
}

// reduce split-K partials for the O projection into d_out
__global__ void reduce_out(float* __restrict__ out, int total4) {
    int i = blockIdx.x * blockDim.x + threadIdx.x;
    if (i >= total4) return;
    float4 r = make_float4(0.f, 0.f, 0.f, 0.f);
    #pragma unroll
    for (int s = 0; s < SPLITK; s++) {
        float4 x = *(const float4*)&g_part[(size_t)s * (B_ * H_) + i * 4];
        r.x += x.x; r.y += x.y; r.z += x.z; r.w += x.w;
    }
    ((float4*)out)[i] = r;
}

// ============================================================
// split-K reduce (QKV) + RMSNorm + NeoX RoPE + scatter k,v.
// ============================================================
__global__ void norm_rope_scatter(const float* __restrict__ q_norm_w,
                                  const float* __restrict__ k_norm_w,
                                  const int* __restrict__ position_ids,
                                  const int* __restrict__ out_cache_loc,
                                  float* __restrict__ k_buf,
                                  float* __restrict__ v_buf) {
    const int head = blockIdx.x;
    const int b = blockIdx.y;
    const int tid = threadIdx.x;
    const int off = b * QKVN + head * D_ + tid;

    float x = 0.f;
    #pragma unroll
    for (int s = 0; s < SPLITK; s++) x += g_part[(size_t)s * (B_ * QKVN) + off];

    if (head >= NH_ + NKV_) {
        int h = head - (NH_ + NKV_);
        int loc = out_cache_loc[b];
        v_buf[(((size_t)b * KV_ + loc) * NKV_ + h) * D_ + tid] = x;
        return;
    }

    __shared__ float sred[4];
    float ss = x * x;
    #pragma unroll
    for (int o = 16; o; o >>= 1) ss += __shfl_xor_sync(0xffffffffu, ss, o);
    if ((tid & 31) == 0) sred[tid >> 5] = ss;
    __syncthreads();
    float total = sred[0] + sred[1] + sred[2] + sred[3];
    float rms = rsqrtf(total * (1.0f / D_) + 1e-6f);
    const float* wn = (head < NH_) ? q_norm_w : k_norm_w;
    float y = x * rms * wn[tid];

    __shared__ float ys[128];
    ys[tid] = y;
    __syncthreads();
    int i = tid & 63;
    double invf = pow(1.0e6, -(double)i / 64.0);
    double ang = (double)position_ids[b] * invf;
    float c = (float)cos(ang), s = (float)sin(ang);
    float outv = (tid < 64) ? (ys[tid] * c - ys[tid + 64] * s)
                            : (ys[tid] * c + ys[tid - 64] * s);

    if (head < NH_) {
        g_qkv[off] = outv;
    } else {
        int h = head - NH_;
        int loc = out_cache_loc[b];
        k_buf[(((size_t)b * KV_ + loc) * NKV_ + h) * D_ + tid] = outv;
    }
}

// ============================================================
// Fused flash-decode chunk: scores + local softmax + PV partial.
// grid (chunk=16, h=8, b=32) = 4096 blocks, 256 threads.
// Scores: 8 lanes per slot (warp covers 4 slots) — coalesced K loads
// AND only 3 shuffle levels per reduction.
// ============================================================
__global__ __launch_bounds__(256) void attn_chunk_kernel(
        const float* __restrict__ k_buf, const float* __restrict__ v_buf) {
    const int chunk = blockIdx.x, h = blockIdx.y, b = blockIdx.z;
    const int tid = threadIdx.x;
    const int warp = tid >> 5, lane = tid & 31;

    // 8 KB buffer aliased by phase (sc: 4 KB, psh: 8 KB)
    __shared__ float sbuf[4 * G_ * 64 * 2];
    float (*sc)[CS] = (float(*)[CS])sbuf;
    __shared__ float sq[G_][D_];       // staged q (2 KB)
    __shared__ float wred[G_][8];
    __shared__ float gm[G_], gs[G_];

    // ---- stage q for the 4 GQA heads ----
    #pragma unroll
    for (int i = tid; i < G_ * D_; i += 256)
        sq[i >> 7][i & 127] = g_qkv[b * QKVN + (h * G_ + (i >> 7)) * D_ + (i & 127)];
    __syncthreads();

    // ---- scores: 8 lanes/slot, 4 slots/warp, 3-level butterfly ----
    const int s0 = chunk * CS;
    {
        const int l8 = lane & 7;       // lane within slot group
        const int sg8 = lane >> 3;     // slot within warp's group of 4
        #pragma unroll 2
        for (int i0 = warp * 4; i0 < CS; i0 += 32) {
            const int slot = i0 + sg8;
            const float* kp = &k_buf[(((size_t)b * KV_ + s0 + slot) * NKV_ + h) * D_ + l8 * 4];
            float dot[G_] = {0.f, 0.f, 0.f, 0.f};
            #pragma unroll
            for (int it = 0; it < 4; it++) {
                float4 kv = *(const float4*)(kp + it * 32);
                #pragma unroll
                for (int g = 0; g < G_; g++) {
                    float4 qv = *(const float4*)&sq[g][it * 32 + l8 * 4];
                    dot[g] += qv.x * kv.x + qv.y * kv.y + qv.z * kv.z + qv.w * kv.w;
                }
            }
            #pragma unroll
            for (int g = 0; g < G_; g++) {
                #pragma unroll
                for (int o = 1; o < 8; o <<= 1)
                    dot[g] += __shfl_xor_sync(0xffffffffu, dot[g], o);
            }
            if (l8 == 0) {
                #pragma unroll
                for (int g = 0; g < G_; g++) sc[g][slot] = dot[g] * SCALE_;
            }
        }
    }
    __syncthreads();

    // ---- local softmax stats: 64 threads (2 warps) per g ----
    {
        const int g = tid >> 6;
        const int j = tid & 63;
        float m = -1e30f;
        #pragma unroll
        for (int e = 0; e < CS / 64; e++) m = fmaxf(m, sc[g][j + e * 64]);
        #pragma unroll
        for (int o = 16; o; o >>= 1) m = fmaxf(m, __shfl_xor_sync(0xffffffffu, m, o));
        if (lane == 0) wred[g][warp & 1] = m;
        __syncthreads();
        m = fmaxf(wred[g][0], wred[g][1]);

        float sum = 0.f;
        #pragma unroll
        for (int e = 0; e < CS / 64; e++) {
            float ex = __expf(sc[g][j + e * 64] - m);
            sc[g][j + e * 64] = ex;
            sum += ex;
        }
        #pragma unroll
        for (int o = 16; o; o >>= 1) sum += __shfl_xor_sync(0xffffffffu, sum, o);
        if (lane == 0) wred[g][2 + (warp & 1)] = sum;
        __syncthreads();
        if (j == 0) { gm[g] = m; gs[g] = wred[g][2] + wred[g][3]; }
    }
    __syncthreads();

    // ---- PV partial: thread owns dims (2*d2, 2*d2+1); quarter covers 64 slots ----
    const int d2 = tid & 63;
    const int q = tid >> 6;
    float2 acc[G_];
    #pragma unroll
    for (int g = 0; g < G_; g++) acc[g] = make_float2(0.f, 0.f);

    const float* vp = &v_buf[(((size_t)b * KV_ + s0 + q * 64) * NKV_ + h) * D_ + d2 * 2];
    #pragma unroll 8
    for (int sl = 0; sl < 64; sl++) {
        float2 v = *(const float2*)(vp + (size_t)sl * (NKV_ * D_));
        #pragma unroll
        for (int g = 0; g < G_; g++) {
            float p = sc[g][q * 64 + sl];
            acc[g].x += p * v.x;
            acc[g].y += p * v.y;
        }
    }
    __syncthreads();

    float2 (*psh)[G_][64] = (float2(*)[G_][64])sbuf;
    #pragma unroll
    for (int g = 0; g < G_; g++) psh[q][g][d2] = acc[g];
    __syncthreads();

    if (q == 0) {
        const size_t obase = ((((size_t)chunk * B_ + b) * NKV_ + h) * G_) * D_;
        #pragma unroll
        for (int g = 0; g < G_; g++) {
            float2 r0 = psh[0][g][d2], r1 = psh[1][g][d2];
            float2 r2 = psh[2][g][d2], r3 = psh[3][g][d2];
            float2 r = make_float2(r0.x + r1.x + r2.x + r3.x,
                                   r0.y + r1.y + r2.y + r3.y);
            *(float2*)&g_opart[obase + g * D_ + d2 * 2] = r;
        }
        if (d2 < G_) {
            size_t msb = ((((size_t)chunk * B_ + b) * NKV_ + h) * G_ + d2) * 2;
            g_ms[msb] = gm[d2];
            g_ms[msb + 1] = gs[d2];
        }
    }
}

// ============================================================
// Combine chunk partials: grid (NH=32, b=32), 128 threads.
// ============================================================
__global__ void attn_combine_kernel() {
    const int head = blockIdx.x;
    const int b = blockIdx.y;
    const int h = head >> 2, g = head & 3;
    const int d = threadIdx.x;

    float M = -1e30f;
    float mloc[NCHUNK];
    #pragma unroll
    for (int c = 0; c < NCHUNK; c++) {
        size_t msb = ((((size_t)c * B_ + b) * NKV_ + h) * G_ + g) * 2;
        mloc[c] = g_ms[msb];
        M = fmaxf(M, mloc[c]);
    }
    float S = 0.f, o = 0.f;
    #pragma unroll
    for (int c = 0; c < NCHUNK; c++) {
        size_t msb = ((((size_t)c * B_ + b) * NKV_ + h) * G_ + g) * 2;
        float w = __expf(mloc[c] - M);
        S += g_ms[msb + 1] * w;
        o += g_opart[(((((size_t)c * B_ + b) * NKV_ + h) * G_ + g)) * D_ + d] * w;
    }
    g_o[b * (NH_ * D_) + head * D_ + d] = o / S;
}

// ============================================================
extern "C" void kernel_launch(void* const* d_in, const int* in_sizes, int n_in,
                              void* d_out, int out_size) {
    const int*   position_ids  = (const int*)  d_in[0];
    const float* hidden_states = (const float*)d_in[1];
    float*       k_buffer      = (float*)      d_in[2];
    float*       v_buffer      = (float*)      d_in[3];
    const int*   out_cache_loc = (const int*)  d_in[4];
    const float* wqkv          = (const float*)d_in[5];
    const float* wo            = (const float*)d_in[6];
    const float* q_norm_w      = (const float*)d_in[7];
    const float* k_norm_w      = (const float*)d_in[8];
    float* out = (float*)d_out;

    float* part_ptr; cudaGetSymbolAddress((void**)&part_ptr, g_part);
    float* o_ptr;    cudaGetSymbolAddress((void**)&o_ptr, g_o);

    // 1. QKV projection (split-K partials)
    gemm_splitk<<<dim3(QKVN / 128, SPLITK), 256>>>(hidden_states, wqkv, part_ptr, QKVN, H_);
    // 2. reduce + RMSNorm + RoPE + scatter
    norm_rope_scatter<<<dim3(NH_ + 2 * NKV_, B_), 128>>>(
        q_norm_w, k_norm_w, position_ids, out_cache_loc, k_buffer, v_buffer);
    // 3. fused flash-decode (split-KV, 8-lane-group scores)
    attn_chunk_kernel<<<dim3(NCHUNK, NKV_, B_), 256>>>(k_buffer, v_buffer);
    // 4. combine partials
    attn_combine_kernel<<<dim3(NH_, B_), 128>>>();
    // 5. O projection + reduce
    gemm_splitk<<<dim3(H_ / 128, SPLITK), 256>>>(o_ptr, wo, part_ptr, H_, H_);
    reduce_out<<<(B_ * H_ / 4 + 255) / 256, 256>>>(out, B_ * H_ / 4);
}

// round 9
// speedup vs baseline: 1.1435x; 1.1435x over previous
#include <cuda_runtime.h>
#include <math.h>

#define B_   32
#define KV_  4096
#define H_   4096
#define NH_  32
#define NKV_ 8
#define D_   128
#define G_   4
#define QKVN ((NH_ + 2*NKV_) * D_)   // 6144
#define SCALE_ 0.08838834764831845f  // 128^-0.5
#define SPLITK 8
#define NCHUNK 16
#define CS     (KV_ / NCHUNK)        // 256 slots per chunk

// ---- scratch (device globals: no allocation) ----
__device__ float g_qkv[B_ * QKVN];                       // roped q
__device__ float g_part[SPLITK * B_ * QKVN];             // split-K GEMM partials
__device__ float g_opart[NCHUNK * B_ * NKV_ * G_ * D_];  // attn partial o
__device__ float g_ms[NCHUNK * B_ * NKV_ * G_ * 2];      // attn partial (m, sum)
__device__ float g_o[B_ * NH_ * D_];                     // attention output

// ============================================================
// Split-K GEMM (fp32 FFMA) with register-prefetch double buffering.
// ============================================================
__global__ __launch_bounds__(256) void gemm_splitk(
        const float* __restrict__ A, const float* __restrict__ W,
        float* __restrict__ P, int N, int K) {
    __shared__ float As[32][36];
    __shared__ float Ws[32][132];
    const int tid = threadIdx.x;
    const int tx = tid & 31;
    const int ty = tid >> 5;
    const int n0 = blockIdx.x * 128;
    const int kslice = K / SPLITK;
    const int kbase = blockIdx.y * kslice;

    const int m_a = tid >> 3, c_a = (tid & 7) * 4;
    const float* Aptr = &A[m_a * K + kbase + c_a];
    const float* Wptr[4];
    int n_w[4], c_w[4];
    #pragma unroll
    for (int j = 0; j < 4; j++) {
        int f = tid + j * 256;
        n_w[j] = f >> 3; c_w[j] = (f & 7) * 4;
        Wptr[j] = &W[(size_t)(n0 + n_w[j]) * K + kbase + c_w[j]];
    }

    float acc[4][4];
    #pragma unroll
    for (int i = 0; i < 4; i++)
        #pragma unroll
        for (int j = 0; j < 4; j++) acc[i][j] = 0.f;

    float4 a_reg = *(const float4*)Aptr;
    float4 w_reg[4];
    #pragma unroll
    for (int j = 0; j < 4; j++) w_reg[j] = *(const float4*)Wptr[j];

    const int nchunks = kslice / 32;
    for (int ck = 0; ck < nchunks; ck++) {
        As[c_a + 0][m_a] = a_reg.x; As[c_a + 1][m_a] = a_reg.y;
        As[c_a + 2][m_a] = a_reg.z; As[c_a + 3][m_a] = a_reg.w;
        #pragma unroll
        for (int j = 0; j < 4; j++) {
            Ws[c_w[j] + 0][n_w[j]] = w_reg[j].x;
            Ws[c_w[j] + 1][n_w[j]] = w_reg[j].y;
            Ws[c_w[j] + 2][n_w[j]] = w_reg[j].z;
            Ws[c_w[j] + 3][n_w[j]] = w_reg[j].w;
        }
        __syncthreads();

        if (ck + 1 < nchunks) {
            a_reg = *(const float4*)(Aptr + (ck + 1) * 32);
            #pragma unroll
            for (int j = 0; j < 4; j++)
                w_reg[j] = *(const float4*)(Wptr[j] + (ck + 1) * 32);
        }

        #pragma unroll
        for (int kk = 0; kk < 32; kk++) {
            float4 a4 = *(const float4*)&As[kk][ty * 4];
            float4 b4 = *(const float4*)&Ws[kk][tx * 4];
            float av[4] = {a4.x, a4.y, a4.z, a4.w};
            float bv[4] = {b4.x, b4.y, b4.z, b4.w};
            #pragma unroll
            for (int i = 0; i < 4; i++)
                #pragma unroll
                for (int j = 0; j < 4; j++) acc[i][j] += av[i] * bv[j];
        }
        __syncthreads();
    }
    float* p = P + (size_t)blockIdx.y * 32 * N;
    #pragma unroll
    for (int i = 0; i < 4; i++)
        *(float4*)&p[(ty * 4 + i) * N + n0 + tx * 4] =
            make_float4(acc[i][0], acc[i][1], acc[i][2], acc[i][3]);
}

// reduce split-K partials for the O projection into d_out
__global__ void reduce_out(float* __restrict__ out, int total4) {
    int i = blockIdx.x * blockDim.x + threadIdx.x;
    if (i >= total4) return;
    float4 r = make_float4(0.f, 0.f, 0.f, 0.f);
    #pragma unroll
    for (int s = 0; s < SPLITK; s++) {
        float4 x = *(const float4*)&g_part[(size_t)s * (B_ * H_) + i * 4];
        r.x += x.x; r.y += x.y; r.z += x.z; r.w += x.w;
    }
    ((float4*)out)[i] = r;
}

// ============================================================
// v-scatter only: split-K reduce of v heads -> v cache.
// grid (8 vheads, 32 batch), 128 threads.
// ============================================================
__global__ void v_scatter_kernel(const int* __restrict__ out_cache_loc,
                                 float* __restrict__ v_buf) {
    const int h = blockIdx.x;
    const int b = blockIdx.y;
    const int tid = threadIdx.x;
    const int off = b * QKVN + (NH_ + NKV_ + h) * D_ + tid;

    float x = 0.f;
    #pragma unroll
    for (int s = 0; s < SPLITK; s++) x += g_part[(size_t)s * (B_ * QKVN) + off];
    int loc = out_cache_loc[b];
    v_buf[(((size_t)b * KV_ + loc) * NKV_ + h) * D_ + tid] = x;
}

// ============================================================
// split-K reduce (q,k heads) + RMSNorm + NeoX RoPE + k scatter.
// grid (40 heads, 32 batch), 128 threads.
// ============================================================
__global__ void norm_rope_kernel(const float* __restrict__ q_norm_w,
                                 const float* __restrict__ k_norm_w,
                                 const int* __restrict__ position_ids,
                                 const int* __restrict__ out_cache_loc,
                                 float* __restrict__ k_buf) {
    const int head = blockIdx.x;       // 0..39: q heads then k heads
    const int b = blockIdx.y;
    const int tid = threadIdx.x;
    const int off = b * QKVN + head * D_ + tid;

    float x = 0.f;
    #pragma unroll
    for (int s = 0; s < SPLITK; s++) x += g_part[(size_t)s * (B_ * QKVN) + off];

    __shared__ float sred[4];
    float ss = x * x;
    #pragma unroll
    for (int o = 16; o; o >>= 1) ss += __shfl_xor_sync(0xffffffffu, ss, o);
    if ((tid & 31) == 0) sred[tid >> 5] = ss;
    __syncthreads();
    float total = sred[0] + sred[1] + sred[2] + sred[3];
    float rms = rsqrtf(total * (1.0f / D_) + 1e-6f);
    const float* wn = (head < NH_) ? q_norm_w : k_norm_w;
    float y = x * rms * wn[tid];

    __shared__ float ys[128];
    ys[tid] = y;
    __syncthreads();
    int i = tid & 63;
    double invf = pow(1.0e6, -(double)i / 64.0);
    double ang = (double)position_ids[b] * invf;
    float c = (float)cos(ang), s = (float)sin(ang);
    float outv = (tid < 64) ? (ys[tid] * c - ys[tid + 64] * s)
                            : (ys[tid] * c + ys[tid - 64] * s);

    if (head < NH_) {
        g_qkv[off] = outv;
    } else {
        int h = head - NH_;
        int loc = out_cache_loc[b];
        k_buf[(((size_t)b * KV_ + loc) * NKV_ + h) * D_ + tid] = outv;
    }
}

// ============================================================
// Fused flash-decode chunk (R5 version — best measured).
// grid (chunk=16, h=8, b=32) = 4096 blocks, 256 threads.
// ============================================================
__global__ __launch_bounds__(256) void attn_chunk_kernel(
        const float* __restrict__ k_buf, const float* __restrict__ v_buf) {
    const int chunk = blockIdx.x, h = blockIdx.y, b = blockIdx.z;
    const int tid = threadIdx.x;
    const int warp = tid >> 5, lane = tid & 31;

    // 8 KB buffer aliased by phase (sc: 4 KB, psh: 8 KB)
    __shared__ float sbuf[4 * G_ * 64 * 2];
    float (*sc)[CS] = (float(*)[CS])sbuf;
    __shared__ float wred[G_][8];
    __shared__ float gm[G_], gs[G_];

    float4 q4[G_];
    #pragma unroll
    for (int g = 0; g < G_; g++)
        q4[g] = *(const float4*)&g_qkv[b * QKVN + (h * G_ + g) * D_ + lane * 4];

    const int s0 = chunk * CS;
    #pragma unroll 4
    for (int i = warp; i < CS; i += 8) {
        float4 kv = *(const float4*)&k_buf[(((size_t)b * KV_ + s0 + i) * NKV_ + h) * D_ + lane * 4];
        float p[G_];
        #pragma unroll
        for (int g = 0; g < G_; g++)
            p[g] = q4[g].x * kv.x + q4[g].y * kv.y + q4[g].z * kv.z + q4[g].w * kv.w;
        #pragma unroll
        for (int g = 0; g < G_; g++)
            #pragma unroll
            for (int o = 16; o; o >>= 1) p[g] += __shfl_xor_sync(0xffffffffu, p[g], o);
        if (lane == 0) {
            #pragma unroll
            for (int g = 0; g < G_; g++) sc[g][i] = p[g] * SCALE_;
        }
    }
    __syncthreads();

    {
        const int g = tid >> 6;
        const int j = tid & 63;
        float m = -1e30f;
        #pragma unroll
        for (int e = 0; e < CS / 64; e++) m = fmaxf(m, sc[g][j + e * 64]);
        #pragma unroll
        for (int o = 16; o; o >>= 1) m = fmaxf(m, __shfl_xor_sync(0xffffffffu, m, o));
        if (lane == 0) wred[g][warp & 1] = m;
        __syncthreads();
        m = fmaxf(wred[g][0], wred[g][1]);

        float sum = 0.f;
        #pragma unroll
        for (int e = 0; e < CS / 64; e++) {
            float ex = __expf(sc[g][j + e * 64] - m);
            sc[g][j + e * 64] = ex;
            sum += ex;
        }
        #pragma unroll
        for (int o = 16; o; o >>= 1) sum += __shfl_xor_sync(0xffffffffu, sum, o);
        if (lane == 0) wred[g][2 + (warp & 1)] = sum;
        __syncthreads();
        if (j == 0) { gm[g] = m; gs[g] = wred[g][2] + wred[g][3]; }
    }
    __syncthreads();

    const int d2 = tid & 63;
    const int q = tid >> 6;
    float2 acc[G_];
    #pragma unroll
    for (int g = 0; g < G_; g++) acc[g] = make_float2(0.f, 0.f);

    const float* vp = &v_buf[(((size_t)b * KV_ + s0 + q * 64) * NKV_ + h) * D_ + d2 * 2];
    #pragma unroll 8
    for (int sl = 0; sl < 64; sl++) {
        float2 v = *(const float2*)(vp + (size_t)sl * (NKV_ * D_));
        #pragma unroll
        for (int g = 0; g < G_; g++) {
            float p = sc[g][q * 64 + sl];
            acc[g].x += p * v.x;
            acc[g].y += p * v.y;
        }
    }
    __syncthreads();

    float2 (*psh)[G_][64] = (float2(*)[G_][64])sbuf;
    #pragma unroll
    for (int g = 0; g < G_; g++) psh[q][g][d2] = acc[g];
    __syncthreads();

    if (q == 0) {
        const size_t obase = ((((size_t)chunk * B_ + b) * NKV_ + h) * G_) * D_;
        #pragma unroll
        for (int g = 0; g < G_; g++) {
            float2 r0 = psh[0][g][d2], r1 = psh[1][g][d2];
            float2 r2 = psh[2][g][d2], r3 = psh[3][g][d2];
            float2 r = make_float2(r0.x + r1.x + r2.x + r3.x,
                                   r0.y + r1.y + r2.y + r3.y);
            *(float2*)&g_opart[obase + g * D_ + d2 * 2] = r;
        }
        if (d2 < G_) {
            size_t msb = ((((size_t)chunk * B_ + b) * NKV_ + h) * G_ + d2) * 2;
            g_ms[msb] = gm[d2];
            g_ms[msb + 1] = gs[d2];
        }
    }
}

// ============================================================
// Combine chunk partials: grid (NH=32, b=32), 128 threads.
// ============================================================
__global__ void attn_combine_kernel() {
    const int head = blockIdx.x;
    const int b = blockIdx.y;
    const int h = head >> 2, g = head & 3;
    const int d = threadIdx.x;

    float M = -1e30f;
    float mloc[NCHUNK];
    #pragma unroll
    for (int c = 0; c < NCHUNK; c++) {
        size_t msb = ((((size_t)c * B_ + b) * NKV_ + h) * G_ + g) * 2;
        mloc[c] = g_ms[msb];
        M = fmaxf(M, mloc[c]);
    }
    float S = 0.f, o = 0.f;
    #pragma unroll
    for (int c = 0; c < NCHUNK; c++) {
        size_t msb = ((((size_t)c * B_ + b) * NKV_ + h) * G_ + g) * 2;
        float w = __expf(mloc[c] - M);
        S += g_ms[msb + 1] * w;
        o += g_opart[(((((size_t)c * B_ + b) * NKV_ + h) * G_ + g)) * D_ + d] * w;
    }
    g_o[b * (NH_ * D_) + head * D_ + d] = o / S;
}

// ============================================================
extern "C" void kernel_launch(void* const* d_in, const int* in_sizes, int n_in,
                              void* d_out, int out_size) {
    const int*   position_ids  = (const int*)  d_in[0];
    const float* hidden_states = (const float*)d_in[1];
    float*       k_buffer      = (float*)      d_in[2];
    float*       v_buffer      = (float*)      d_in[3];
    const int*   out_cache_loc = (const int*)  d_in[4];
    const float* wqkv          = (const float*)d_in[5];
    const float* wo            = (const float*)d_in[6];
    const float* q_norm_w      = (const float*)d_in[7];
    const float* k_norm_w      = (const float*)d_in[8];
    float* out = (float*)d_out;

    float* part_ptr; cudaGetSymbolAddress((void**)&part_ptr, g_part);
    float* o_ptr;    cudaGetSymbolAddress((void**)&o_ptr, g_o);

    // 1. QKV projection (split-K partials)
    gemm_splitk<<<dim3(QKVN / 128, SPLITK), 256>>>(hidden_states, wqkv, part_ptr, QKVN, H_);
    // 2. reduce + RMSNorm + RoPE (q,k) + k scatter
    norm_rope_kernel<<<dim3(NH_ + NKV_, B_), 128>>>(
        q_norm_w, k_norm_w, position_ids, out_cache_loc, k_buffer);
    // 3. v scatter (separate so attn_chunk is the 4th launch -> gets profiled)
    v_scatter_kernel<<<dim3(NKV_, B_), 128>>>(out_cache_loc, v_buffer);
    // 4. fused flash-decode (split-KV) — profiler target
    attn_chunk_kernel<<<dim3(NCHUNK, NKV_, B_), 256>>>(k_buffer, v_buffer);
    // 5. combine partials
    attn_combine_kernel<<<dim3(NH_, B_), 128>>>();
    // 6. O projection + reduce
    gemm_splitk<<<dim3(H_ / 128, SPLITK), 256>>>(o_ptr, wo, part_ptr, H_, H_);
    reduce_out<<<(B_ * H_ / 4 + 255) / 256, 256>>>(out, B_ * H_ / 4);
}

// round 10
// speedup vs baseline: 1.2620x; 1.1036x over previous
#include <cuda_runtime.h>
#include <math.h>

#define B_   32
#define KV_  4096
#define H_   4096
#define NH_  32
#define NKV_ 8
#define D_   128
#define G_   4
#define QKVN ((NH_ + 2*NKV_) * D_)   // 6144
#define SCALE_ 0.08838834764831845f  // 128^-0.5
#define SPLITK 8
#define NCHUNK 16
#define CS     (KV_ / NCHUNK)        // 256 slots per chunk

// ---- scratch (device globals: no allocation) ----
__device__ float  g_qkv[B_ * QKVN];
__device__ float  g_part[SPLITK * B_ * QKVN];
__device__ float  g_opart[NCHUNK * B_ * NKV_ * G_ * D_];
__device__ float  g_ms[NCHUNK * B_ * NKV_ * G_ * 2];
__device__ float  g_o[B_ * NH_ * D_];
__device__ double g_invf[64];           // RoPE inverse frequencies (double)
__device__ float  g_cosb[B_][64];       // per-batch cos table
__device__ float  g_sinb[B_][64];       // per-batch sin table

// ---- tiny prelaunch kernels (also steer profiler: gemm becomes launch #4) ----
__global__ void rope_invf_kernel() {
    int i = threadIdx.x;
    if (i < 64) g_invf[i] = pow(1.0e6, -(double)i / 64.0);
}
__global__ void rope_cos_kernel(const int* __restrict__ position_ids) {
    int b = blockIdx.x, i = threadIdx.x;
    g_cosb[b][i] = (float)cos((double)position_ids[b] * g_invf[i]);
}
__global__ void rope_sin_kernel(const int* __restrict__ position_ids) {
    int b = blockIdx.x, i = threadIdx.x;
    g_sinb[b][i] = (float)sin((double)position_ids[b] * g_invf[i]);
}

// ============================================================
// Split-K GEMM (fp32 FFMA) with register-prefetch double buffering.
// (byte-identical structure to R9 — this is the profiling target)
// ============================================================
__global__ __launch_bounds__(256) void gemm_splitk(
        const float* __restrict__ A, const float* __restrict__ W,
        float* __restrict__ P, int N, int K) {
    __shared__ float As[32][36];
    __shared__ float Ws[32][132];
    const int tid = threadIdx.x;
    const int tx = tid & 31;
    const int ty = tid >> 5;
    const int n0 = blockIdx.x * 128;
    const int kslice = K / SPLITK;
    const int kbase = blockIdx.y * kslice;

    const int m_a = tid >> 3, c_a = (tid & 7) * 4;
    const float* Aptr = &A[m_a * K + kbase + c_a];
    const float* Wptr[4];
    int n_w[4], c_w[4];
    #pragma unroll
    for (int j = 0; j < 4; j++) {
        int f = tid + j * 256;
        n_w[j] = f >> 3; c_w[j] = (f & 7) * 4;
        Wptr[j] = &W[(size_t)(n0 + n_w[j]) * K + kbase + c_w[j]];
    }

    float acc[4][4];
    #pragma unroll
    for (int i = 0; i < 4; i++)
        #pragma unroll
        for (int j = 0; j < 4; j++) acc[i][j] = 0.f;

    float4 a_reg = *(const float4*)Aptr;
    float4 w_reg[4];
    #pragma unroll
    for (int j = 0; j < 4; j++) w_reg[j] = *(const float4*)Wptr[j];

    const int nchunks = kslice / 32;
    for (int ck = 0; ck < nchunks; ck++) {
        As[c_a + 0][m_a] = a_reg.x; As[c_a + 1][m_a] = a_reg.y;
        As[c_a + 2][m_a] = a_reg.z; As[c_a + 3][m_a] = a_reg.w;
        #pragma unroll
        for (int j = 0; j < 4; j++) {
            Ws[c_w[j] + 0][n_w[j]] = w_reg[j].x;
            Ws[c_w[j] + 1][n_w[j]] = w_reg[j].y;
            Ws[c_w[j] + 2][n_w[j]] = w_reg[j].z;
            Ws[c_w[j] + 3][n_w[j]] = w_reg[j].w;
        }
        __syncthreads();

        if (ck + 1 < nchunks) {
            a_reg = *(const float4*)(Aptr + (ck + 1) * 32);
            #pragma unroll
            for (int j = 0; j < 4; j++)
                w_reg[j] = *(const float4*)(Wptr[j] + (ck + 1) * 32);
        }

        #pragma unroll
        for (int kk = 0; kk < 32; kk++) {
            float4 a4 = *(const float4*)&As[kk][ty * 4];
            float4 b4 = *(const float4*)&Ws[kk][tx * 4];
            float av[4] = {a4.x, a4.y, a4.z, a4.w};
            float bv[4] = {b4.x, b4.y, b4.z, b4.w};
            #pragma unroll
            for (int i = 0; i < 4; i++)
                #pragma unroll
                for (int j = 0; j < 4; j++) acc[i][j] += av[i] * bv[j];
        }
        __syncthreads();
    }
    float* p = P + (size_t)blockIdx.y * 32 * N;
    #pragma unroll
    for (int i = 0; i < 4; i++)
        *(float4*)&p[(ty * 4 + i) * N + n0 + tx * 4] =
            make_float4(acc[i][0], acc[i][1], acc[i][2], acc[i][3]);
}

// reduce split-K partials for the O projection into d_out
__global__ void reduce_out(float* __restrict__ out, int total4) {
    int i = blockIdx.x * blockDim.x + threadIdx.x;
    if (i >= total4) return;
    float4 r = make_float4(0.f, 0.f, 0.f, 0.f);
    #pragma unroll
    for (int s = 0; s < SPLITK; s++) {
        float4 x = *(const float4*)&g_part[(size_t)s * (B_ * H_) + i * 4];
        r.x += x.x; r.y += x.y; r.z += x.z; r.w += x.w;
    }
    ((float4*)out)[i] = r;
}

// ============================================================
// split-K reduce + RMSNorm + RoPE (tables) + k,v scatter.
// grid (48 heads, 32 batch), 128 threads.
// ============================================================
__global__ void norm_rope_scatter(const float* __restrict__ q_norm_w,
                                  const float* __restrict__ k_norm_w,
                                  const int* __restrict__ out_cache_loc,
                                  float* __restrict__ k_buf,
                                  float* __restrict__ v_buf) {
    const int head = blockIdx.x;
    const int b = blockIdx.y;
    const int tid = threadIdx.x;
    const int off = b * QKVN + head * D_ + tid;

    float x = 0.f;
    #pragma unroll
    for (int s = 0; s < SPLITK; s++) x += g_part[(size_t)s * (B_ * QKVN) + off];

    if (head >= NH_ + NKV_) {
        int h = head - (NH_ + NKV_);
        int loc = out_cache_loc[b];
        v_buf[(((size_t)b * KV_ + loc) * NKV_ + h) * D_ + tid] = x;
        return;
    }

    __shared__ float sred[4];
    float ss = x * x;
    #pragma unroll
    for (int o = 16; o; o >>= 1) ss += __shfl_xor_sync(0xffffffffu, ss, o);
    if ((tid & 31) == 0) sred[tid >> 5] = ss;
    __syncthreads();
    float total = sred[0] + sred[1] + sred[2] + sred[3];
    float rms = rsqrtf(total * (1.0f / D_) + 1e-6f);
    const float* wn = (head < NH_) ? q_norm_w : k_norm_w;
    float y = x * rms * wn[tid];

    __shared__ float ys[128];
    ys[tid] = y;
    __syncthreads();
    int i = tid & 63;
    float c = g_cosb[b][i], s = g_sinb[b][i];
    float outv = (tid < 64) ? (ys[tid] * c - ys[tid + 64] * s)
                            : (ys[tid] * c + ys[tid - 64] * s);

    if (head < NH_) {
        g_qkv[off] = outv;
    } else {
        int h = head - NH_;
        int loc = out_cache_loc[b];
        k_buf[(((size_t)b * KV_ + loc) * NKV_ + h) * D_ + tid] = outv;
    }
}

// ============================================================
// Fused flash-decode chunk (best-measured R5/R9 form — unchanged).
// ============================================================
__global__ __launch_bounds__(256) void attn_chunk_kernel(
        const float* __restrict__ k_buf, const float* __restrict__ v_buf) {
    const int chunk = blockIdx.x, h = blockIdx.y, b = blockIdx.z;
    const int tid = threadIdx.x;
    const int warp = tid >> 5, lane = tid & 31;

    __shared__ float sbuf[4 * G_ * 64 * 2];
    float (*sc)[CS] = (float(*)[CS])sbuf;
    __shared__ float wred[G_][8];
    __shared__ float gm[G_], gs[G_];

    float4 q4[G_];
    #pragma unroll
    for (int g = 0; g < G_; g++)
        q4[g] = *(const float4*)&g_qkv[b * QKVN + (h * G_ + g) * D_ + lane * 4];

    const int s0 = chunk * CS;
    #pragma unroll 4
    for (int i = warp; i < CS; i += 8) {
        float4 kv = *(const float4*)&k_buf[(((size_t)b * KV_ + s0 + i) * NKV_ + h) * D_ + lane * 4];
        float p[G_];
        #pragma unroll
        for (int g = 0; g < G_; g++)
            p[g] = q4[g].x * kv.x + q4[g].y * kv.y + q4[g].z * kv.z + q4[g].w * kv.w;
        #pragma unroll
        for (int g = 0; g < G_; g++)
            #pragma unroll
            for (int o = 16; o; o >>= 1) p[g] += __shfl_xor_sync(0xffffffffu, p[g], o);
        if (lane == 0) {
            #pragma unroll
            for (int g = 0; g < G_; g++) sc[g][i] = p[g] * SCALE_;
        }
    }
    __syncthreads();

    {
        const int g = tid >> 6;
        const int j = tid & 63;
        float m = -1e30f;
        #pragma unroll
        for (int e = 0; e < CS / 64; e++) m = fmaxf(m, sc[g][j + e * 64]);
        #pragma unroll
        for (int o = 16; o; o >>= 1) m = fmaxf(m, __shfl_xor_sync(0xffffffffu, m, o));
        if (lane == 0) wred[g][warp & 1] = m;
        __syncthreads();
        m = fmaxf(wred[g][0], wred[g][1]);

        float sum = 0.f;
        #pragma unroll
        for (int e = 0; e < CS / 64; e++) {
            float ex = __expf(sc[g][j + e * 64] - m);
            sc[g][j + e * 64] = ex;
            sum += ex;
        }
        #pragma unroll
        for (int o = 16; o; o >>= 1) sum += __shfl_xor_sync(0xffffffffu, sum, o);
        if (lane == 0) wred[g][2 + (warp & 1)] = sum;
        __syncthreads();
        if (j == 0) { gm[g] = m; gs[g] = wred[g][2] + wred[g][3]; }
    }
    __syncthreads();

    const int d2 = tid & 63;
    const int q = tid >> 6;
    float2 acc[G_];
    #pragma unroll
    for (int g = 0; g < G_; g++) acc[g] = make_float2(0.f, 0.f);

    const float* vp = &v_buf[(((size_t)b * KV_ + s0 + q * 64) * NKV_ + h) * D_ + d2 * 2];
    #pragma unroll 8
    for (int sl = 0; sl < 64; sl++) {
        float2 v = *(const float2*)(vp + (size_t)sl * (NKV_ * D_));
        #pragma unroll
        for (int g = 0; g < G_; g++) {
            float p = sc[g][q * 64 + sl];
            acc[g].x += p * v.x;
            acc[g].y += p * v.y;
        }
    }
    __syncthreads();

    float2 (*psh)[G_][64] = (float2(*)[G_][64])sbuf;
    #pragma unroll
    for (int g = 0; g < G_; g++) psh[q][g][d2] = acc[g];
    __syncthreads();

    if (q == 0) {
        const size_t obase = ((((size_t)chunk * B_ + b) * NKV_ + h) * G_) * D_;
        #pragma unroll
        for (int g = 0; g < G_; g++) {
            float2 r0 = psh[0][g][d2], r1 = psh[1][g][d2];
            float2 r2 = psh[2][g][d2], r3 = psh[3][g][d2];
            float2 r = make_float2(r0.x + r1.x + r2.x + r3.x,
                                   r0.y + r1.y + r2.y + r3.y);
            *(float2*)&g_opart[obase + g * D_ + d2 * 2] = r;
        }
        if (d2 < G_) {
            size_t msb = ((((size_t)chunk * B_ + b) * NKV_ + h) * G_ + d2) * 2;
            g_ms[msb] = gm[d2];
            g_ms[msb + 1] = gs[d2];
        }
    }
}

// ============================================================
// Combine chunk partials: grid (NH=32, b=32), 128 threads.
// ============================================================
__global__ void attn_combine_kernel() {
    const int head = blockIdx.x;
    const int b = blockIdx.y;
    const int h = head >> 2, g = head & 3;
    const int d = threadIdx.x;

    float M = -1e30f;
    float mloc[NCHUNK];
    #pragma unroll
    for (int c = 0; c < NCHUNK; c++) {
        size_t msb = ((((size_t)c * B_ + b) * NKV_ + h) * G_ + g) * 2;
        mloc[c] = g_ms[msb];
        M = fmaxf(M, mloc[c]);
    }
    float S = 0.f, o = 0.f;
    #pragma unroll
    for (int c = 0; c < NCHUNK; c++) {
        size_t msb = ((((size_t)c * B_ + b) * NKV_ + h) * G_ + g) * 2;
        float w = __expf(mloc[c] - M);
        S += g_ms[msb + 1] * w;
        o += g_opart[(((((size_t)c * B_ + b) * NKV_ + h) * G_ + g)) * D_ + d] * w;
    }
    g_o[b * (NH_ * D_) + head * D_ + d] = o / S;
}

// ============================================================
extern "C" void kernel_launch(void* const* d_in, const int* in_sizes, int n_in,
                              void* d_out, int out_size) {
    const int*   position_ids  = (const int*)  d_in[0];
    const float* hidden_states = (const float*)d_in[1];
    float*       k_buffer      = (float*)      d_in[2];
    float*       v_buffer      = (float*)      d_in[3];
    const int*   out_cache_loc = (const int*)  d_in[4];
    const float* wqkv          = (const float*)d_in[5];
    const float* wo            = (const float*)d_in[6];
    const float* q_norm_w      = (const float*)d_in[7];
    const float* k_norm_w      = (const float*)d_in[8];
    float* out = (float*)d_out;

    float* part_ptr; cudaGetSymbolAddress((void**)&part_ptr, g_part);
    float* o_ptr;    cudaGetSymbolAddress((void**)&o_ptr, g_o);

    // 1-3. RoPE tables (tiny; also place the QKV GEMM in profiler slot 4)
    rope_invf_kernel<<<1, 64>>>();
    rope_cos_kernel<<<B_, 64>>>(position_ids);
    rope_sin_kernel<<<B_, 64>>>(position_ids);
    // 4. QKV projection — PROFILED THIS ROUND
    gemm_splitk<<<dim3(QKVN / 128, SPLITK), 256>>>(hidden_states, wqkv, part_ptr, QKVN, H_);
    // 5. reduce + RMSNorm + RoPE + k,v scatter
    norm_rope_scatter<<<dim3(NH_ + 2 * NKV_, B_), 128>>>(
        q_norm_w, k_norm_w, out_cache_loc, k_buffer, v_buffer);
    // 6. fused flash-decode (split-KV)
    attn_chunk_kernel<<<dim3(NCHUNK, NKV_, B_), 256>>>(k_buffer, v_buffer);
    // 7. combine partials
    attn_combine_kernel<<<dim3(NH_, B_), 128>>>();
    // 8. O projection + 9. reduce
    gemm_splitk<<<dim3(H_ / 128, SPLITK), 256>>>(o_ptr, wo, part_ptr, H_, H_);
    reduce_out<<<(B_ * H_ / 4 + 255) / 256, 256>>>(out, B_ * H_ / 4);
}